// round 8
// baseline (speedup 1.0000x reference)
#include <cuda_runtime.h>
#include <math.h>

// NarrowParabolicEq — precomputed banded Dopri5 step operator, register-built.
// S = P + iQ, P = I - c2 Z^2 + c4 Z^4 - c6 Z^6 (radius 6), Q = Z - c3 Z^3 + c5 Z^5
// (radius 5), Z = real tridiagonal h*zeta. Each thread builds its OWN band row
// of P,Q in registers via the banded row recurrence with compile-time indices
// only (no dynamic indexing anywhere -> no local-memory demotion).
// Main loop: one 13-pt banded apply + ONE __syncthreads per RK step
// (2000 barriers total). 512 threads, packed f32x2, dual shifted Y copies for
// alignment-uniform LDS.128. Planar complex output.

#define NPTS 500
#define NTH  512
#define YSLOTS 528        // point q -> slot q+6 (copy0) / q+7 (copy1)
#define N_INNER 10

typedef unsigned long long u64;
union F2U { float2 f; u64 u; };

__device__ __forceinline__ u64 pk2(float lo, float hi) { F2U x; x.f.x = lo; x.f.y = hi; return x.u; }
__device__ __forceinline__ float lo2(u64 v) { F2U a; a.u = v; return a.f.x; }
__device__ __forceinline__ float hi2(u64 v) { F2U a; a.u = v; return a.f.y; }

__device__ __forceinline__ u64 fma2(u64 a, u64 b, u64 c)
{ u64 d; asm("fma.rn.f32x2 %0,%1,%2,%3;" : "=l"(d) : "l"(a), "l"(b), "l"(c)); return d; }
__device__ __forceinline__ u64 add2(u64 a, u64 b)
{ u64 d; asm("add.rn.f32x2 %0,%1,%2;" : "=l"(d) : "l"(a), "l"(b)); return d; }
__device__ __forceinline__ u64 mul2(u64 a, u64 b)
{ u64 d; asm("mul.rn.f32x2 %0,%1,%2;" : "=l"(d) : "l"(a), "l"(b)); return d; }

__device__ __forceinline__ void coeffs_at(int q, double K0d, double refc, double refd,
                                          float* hcli, float* hch2)
{
    if (q >= 1 && q <= NPTS - 2) {
        double dx = 2000.0 / 499.0;
        double cli = (1.0 / (dx * dx)) / (2.0 * K0d);
        double z  = 2000.0 * (double)q / 499.0;
        double zz = 2.0 * (z - refd) / refd;
        double c  = refc * (1.0 + 0.00737 * (zz - 1.0 + exp(-zz)));
        double het = (1500.0 / c) * (1500.0 / c) - 1.0;
        double ch = K0d * het;
        *hcli = (float)(0.1 * cli);
        *hch2 = (float)(0.1 * (ch - 2.0 * cli));
    } else {
        *hcli = 0.0f; *hch2 = 0.0f;
    }
}

__global__ __launch_bounds__(NTH, 1)
void pe_kernel(const float* __restrict__ params, float* __restrict__ out, int n_save)
{
    __shared__ __align__(16) u64 YA0[YSLOTS];
    __shared__ __align__(16) u64 YA1[YSLOTS];
    __shared__ __align__(16) u64 YB0[YSLOTS];
    __shared__ __align__(16) u64 YB1[YSLOTS];

    const int p = threadIdx.x;
    const int half = n_save * NPTS;

    const double PI  = 3.14159265358979323846;
    const double K0d = 2.0 * PI * 50.0 / 1500.0;
    const double refc = (double)params[0];
    const double refd = (double)params[1];

    // ---- initial field ----
    float y0r = 0.f;
    if (p < NPTS) {
        double ww  = sqrt(2.0 * log(2.0)) / (K0d * sin(PI / 180.0 * 1.5));
        double amp = 1.0 / (sqrt(PI) * ww);
        double z = 2000.0 * (double)p / 499.0;
        double a = (z - 100.0) / ww;
        y0r = (float)(amp * exp(-a * a));
        out[p] = y0r;
        out[half + p] = 0.f;
    }

    // ---------- build band rows of P,Q in registers (literal indices only) ----------
    float cliA[13], ch2A[13];
    #pragma unroll
    for (int j = 0; j < 13; j++)
        coeffs_at(p - 6 + j, K0d, refc, refd, &cliA[j], &ch2A[j]);

    float w[13], Pr[13], Qr[13];
    #pragma unroll
    for (int j = 0; j < 13; j++) { w[j] = 0.f; Pr[j] = 0.f; Qr[j] = 0.f; }
    w[6] = 1.f; Pr[6] = 1.f;

    #pragma unroll
    for (int k = 1; k <= 6; k++) {
        float nw[13];
        #pragma unroll
        for (int o = 0; o < 13; o++) {
            float acc = w[o] * ch2A[o];
            if (o > 0)  acc += w[o - 1] * cliA[o - 1];
            if (o < 12) acc += w[o + 1] * cliA[o + 1];
            nw[o] = acc;
        }
        // literal coefficients, selected by the UNROLLED loop index (constant-folded)
        #pragma unroll
        for (int o = 0; o < 13; o++) {
            w[o] = nw[o];
            if (k == 1) Qr[o] += nw[o];
            if (k == 2) Pr[o] -= 0.5f * nw[o];
            if (k == 3) Qr[o] -= (float)(1.0/6.0) * nw[o];
            if (k == 4) Pr[o] += (float)(1.0/24.0) * nw[o];
            if (k == 5) Qr[o] += (float)(1.0/120.0) * nw[o];
            if (k == 6) Pr[o] -= (float)(1.0/600.0) * nw[o];
        }
    }

    u64 Pc[13], Qc[11];
    #pragma unroll
    for (int j = 0; j < 13; j++) Pc[j] = pk2(Pr[j], Pr[j]);
    #pragma unroll
    for (int j = 0; j < 11; j++) Qc[j] = pk2(Qr[j + 1], Qr[j + 1]);   // offsets -5..+5

    // ---------- Y buffers ----------
    for (int j = p; j < YSLOTS; j += NTH) { YA0[j]=0; YA1[j]=0; YB0[j]=0; YB1[j]=0; }
    __syncthreads();
    u64 y = pk2(y0r, 0.f);
    YA0[p + 6] = y;
    YA1[p + 7] = y;
    __syncthreads();

    const float4* baseA = (p & 1) ? ((const float4*)YA1) + ((p + 1) >> 1)
                                  : ((const float4*)YA0) + (p >> 1);
    const float4* baseB = (p & 1) ? ((const float4*)YB1) + ((p + 1) >> 1)
                                  : ((const float4*)YB0) + (p >> 1);
    const int nitv = n_save - 1;
    int flip = 0;   // 0: read A write B ; 1: read B write A

    for (int itv = 0; itv < nitv; ++itv) {
        #pragma unroll 1
        for (int st = 0; st < N_INNER; ++st) {
            const float4* B = flip ? baseB : baseA;
            u64* s0 = flip ? YA0 : YB0;
            u64* s1 = flip ? YA1 : YB1;

            u64 v[14];
            #pragma unroll
            for (int j = 0; j < 7; j++) {
                float4 f = B[j];
                v[2*j]     = pk2(f.x, f.y);
                v[2*j + 1] = pk2(f.z, f.w);
            }
            // P y : offsets -6..6 -> Pc[j]*v[j], 4 accumulators
            u64 a0 = mul2(Pc[0], v[0]);
            u64 a1 = mul2(Pc[1], v[1]);
            u64 a2 = mul2(Pc[2], v[2]);
            u64 a3 = mul2(Pc[3], v[3]);
            a0 = fma2(Pc[4],  v[4],  a0);
            a1 = fma2(Pc[5],  v[5],  a1);
            a2 = fma2(Pc[6],  v[6],  a2);
            a3 = fma2(Pc[7],  v[7],  a3);
            a0 = fma2(Pc[8],  v[8],  a0);
            a1 = fma2(Pc[9],  v[9],  a1);
            a2 = fma2(Pc[10], v[10], a2);
            a3 = fma2(Pc[11], v[11], a3);
            a0 = fma2(Pc[12], v[12], a0);
            // Q y : offsets -5..5 -> Qc[j]*v[j+1], 4 accumulators
            u64 q0 = mul2(Qc[0], v[1]);
            u64 q1 = mul2(Qc[1], v[2]);
            u64 q2 = mul2(Qc[2], v[3]);
            u64 q3 = mul2(Qc[3], v[4]);
            q0 = fma2(Qc[4],  v[5],  q0);
            q1 = fma2(Qc[5],  v[6],  q1);
            q2 = fma2(Qc[6],  v[7],  q2);
            q3 = fma2(Qc[7],  v[8],  q3);
            q0 = fma2(Qc[8],  v[9],  q0);
            q1 = fma2(Qc[9],  v[10], q1);
            q2 = fma2(Qc[10], v[11], q2);

            u64 up = add2(add2(a0, a1), add2(a2, a3));
            u64 uq = add2(add2(q0, q1), add2(q2, q3));
            // y' = (P y) + i (Q y)
            F2U U, Qv; U.u = up; Qv.u = uq;
            y = pk2(U.f.x - Qv.f.y, U.f.y + Qv.f.x);

            s0[p + 6] = y;
            s1[p + 7] = y;
            __syncthreads();
            flip ^= 1;
        }
        if (p < NPTS) {
            int row = (itv + 1) * NPTS + p;
            out[row]        = lo2(y);
            out[half + row] = hi2(y);
        }
    }
}

extern "C" void kernel_launch(void* const* d_in, const int* in_sizes, int n_in,
                              void* d_out, int out_size)
{
    int p_idx = 1, t_idx = 0;
    if (n_in >= 2 && in_sizes[0] == 2 && in_sizes[1] != 2) { p_idx = 0; t_idx = 1; }
    const float* params = (const float*)d_in[p_idx];
    const int n_save = in_sizes[t_idx];
    pe_kernel<<<1, NTH>>>(params, (float*)d_out, n_save);
}

// round 9
// speedup vs baseline: 2.3259x; 2.3259x over previous
#include <cuda_runtime.h>
#include <math.h>

// NarrowParabolicEq — banded Dopri5 step operator, 2 points/thread.
// S = P + iQ (P radius 6, Q radius 5, both real) built per-thread in registers
// via the banded row recurrence (literal indices only). Each thread owns TWO
// adjacent points -> halo is 14 u64 = 7 aligned LDS.128 from a SINGLE buffer,
// store is one aligned STS.128. One __syncthreads per RK step (2000 total).
// smem traffic 32KB/step (was 65KB at 1pt/thread). Planar complex output.

#define NPTS 500
#define NTH  256
#define YSLOTS 528        // u64 slots; point q -> slot q+6
#define N_INNER 10

typedef unsigned long long u64;
union F2U { float2 f; u64 u; };

__device__ __forceinline__ u64 pk2(float lo, float hi) { F2U x; x.f.x = lo; x.f.y = hi; return x.u; }
__device__ __forceinline__ float lo2(u64 v) { F2U a; a.u = v; return a.f.x; }
__device__ __forceinline__ float hi2(u64 v) { F2U a; a.u = v; return a.f.y; }

__device__ __forceinline__ u64 fma2(u64 a, u64 b, u64 c)
{ u64 d; asm("fma.rn.f32x2 %0,%1,%2,%3;" : "=l"(d) : "l"(a), "l"(b), "l"(c)); return d; }
__device__ __forceinline__ u64 add2(u64 a, u64 b)
{ u64 d; asm("add.rn.f32x2 %0,%1,%2;" : "=l"(d) : "l"(a), "l"(b)); return d; }
__device__ __forceinline__ u64 mul2(u64 a, u64 b)
{ u64 d; asm("mul.rn.f32x2 %0,%1,%2;" : "=l"(d) : "l"(a), "l"(b)); return d; }

__device__ __forceinline__ void coeffs_at(int q, double K0d, double refc, double refd,
                                          float* hcli, float* hch2)
{
    if (q >= 1 && q <= NPTS - 2) {
        double dx = 2000.0 / 499.0;
        double cli = (1.0 / (dx * dx)) / (2.0 * K0d);
        double z  = 2000.0 * (double)q / 499.0;
        double zz = 2.0 * (z - refd) / refd;
        double c  = refc * (1.0 + 0.00737 * (zz - 1.0 + exp(-zz)));
        double het = (1500.0 / c) * (1500.0 / c) - 1.0;
        double ch = K0d * het;
        *hcli = (float)(0.1 * cli);
        *hch2 = (float)(0.1 * (ch - 2.0 * cli));
    } else {
        *hcli = 0.0f; *hch2 = 0.0f;
    }
}

// Band row of P,Q (offsets -6..+6 around q) via register recurrence.
__device__ __forceinline__ void build_row(int q, double K0d, double refc, double refd,
                                          float Pr[13], float Qr[13])
{
    float cliA[13], ch2A[13];
    #pragma unroll
    for (int j = 0; j < 13; j++)
        coeffs_at(q - 6 + j, K0d, refc, refd, &cliA[j], &ch2A[j]);

    float w[13];
    #pragma unroll
    for (int j = 0; j < 13; j++) { w[j] = 0.f; Pr[j] = 0.f; Qr[j] = 0.f; }
    w[6] = 1.f; Pr[6] = 1.f;

    #pragma unroll
    for (int k = 1; k <= 6; k++) {
        float nw[13];
        #pragma unroll
        for (int o = 0; o < 13; o++) {
            float acc = w[o] * ch2A[o];
            if (o > 0)  acc += w[o - 1] * cliA[o - 1];
            if (o < 12) acc += w[o + 1] * cliA[o + 1];
            nw[o] = acc;
        }
        #pragma unroll
        for (int o = 0; o < 13; o++) {
            w[o] = nw[o];
            if (k == 1) Qr[o] += nw[o];
            if (k == 2) Pr[o] -= 0.5f * nw[o];
            if (k == 3) Qr[o] -= (float)(1.0/6.0) * nw[o];
            if (k == 4) Pr[o] += (float)(1.0/24.0) * nw[o];
            if (k == 5) Qr[o] += (float)(1.0/120.0) * nw[o];
            if (k == 6) Pr[o] -= (float)(1.0/600.0) * nw[o];
        }
    }
}

__global__ __launch_bounds__(NTH, 1)
void pe_kernel(const float* __restrict__ params, float* __restrict__ out, int n_save)
{
    __shared__ __align__(16) u64 YA[YSLOTS];
    __shared__ __align__(16) u64 YB[YSLOTS];

    const int t  = threadIdx.x;
    const int p0 = 2 * t;                 // owns points p0, p0+1
    const int half = n_save * NPTS;

    const double PI  = 3.14159265358979323846;
    const double K0d = 2.0 * PI * 50.0 / 1500.0;
    const double refc = (double)params[0];
    const double refd = (double)params[1];

    // ---- initial field ----
    float y0r = 0.f, y1r = 0.f;
    if (p0 < NPTS) {
        double ww  = sqrt(2.0 * log(2.0)) / (K0d * sin(PI / 180.0 * 1.5));
        double amp = 1.0 / (sqrt(PI) * ww);
        double z = 2000.0 * (double)p0 / 499.0;
        double a = (z - 100.0) / ww;
        y0r = (float)(amp * exp(-a * a));
        z = 2000.0 * (double)(p0 + 1) / 499.0;
        a = (z - 100.0) / ww;
        y1r = (float)(amp * exp(-a * a));
        out[p0] = y0r;  out[p0 + 1] = y1r;
        out[half + p0] = 0.f;  out[half + p0 + 1] = 0.f;
    }

    // ---- band rows for both owned points ----
    float Pr0[13], Qr0[13], Pr1[13], Qr1[13];
    build_row(p0,     K0d, refc, refd, Pr0, Qr0);
    build_row(p0 + 1, K0d, refc, refd, Pr1, Qr1);

    u64 Pc0[13], Qc0[11], Pc1[13], Qc1[11];
    #pragma unroll
    for (int j = 0; j < 13; j++) { Pc0[j] = pk2(Pr0[j], Pr0[j]); Pc1[j] = pk2(Pr1[j], Pr1[j]); }
    #pragma unroll
    for (int j = 0; j < 11; j++) { Qc0[j] = pk2(Qr0[j + 1], Qr0[j + 1]); Qc1[j] = pk2(Qr1[j + 1], Qr1[j + 1]); }

    // ---- buffers ----
    for (int j = t; j < YSLOTS; j += NTH) { YA[j] = 0; YB[j] = 0; }
    __syncthreads();
    u64 y0p = pk2(y0r, 0.f), y1p = pk2(y1r, 0.f);
    YA[p0 + 6] = y0p;
    YA[p0 + 7] = y1p;
    __syncthreads();

    const float4* RA = ((const float4*)YA) + t;   // f4 idx t -> u64 slots 2t..2t+1
    const float4* RB = ((const float4*)YB) + t;
    float4* WA = ((float4*)YA) + (t + 3);         // u64 slots 2t+6..2t+7
    float4* WB = ((float4*)YB) + (t + 3);

    // One step: read halo (points p0-6..p0+7) from RSRC, apply S to both points,
    // store to WDST, barrier.  Taps: P0->v[0..12], Q0->v[1..11], P1->v[1..13], Q1->v[2..12].
#define STEP(RSRC, WDST)                                                     \
    {                                                                        \
        u64 v[14];                                                           \
        _Pragma("unroll")                                                    \
        for (int j = 0; j < 7; j++) {                                        \
            float4 f = (RSRC)[j];                                            \
            v[2*j] = pk2(f.x, f.y); v[2*j + 1] = pk2(f.z, f.w);              \
        }                                                                    \
        u64 a0 = mul2(Pc0[0], v[0]);  u64 a1 = mul2(Pc0[1], v[1]);           \
        u64 a2 = mul2(Pc0[2], v[2]);  u64 a3 = mul2(Pc0[3], v[3]);           \
        a0 = fma2(Pc0[4],  v[4],  a0); a1 = fma2(Pc0[5],  v[5],  a1);        \
        a2 = fma2(Pc0[6],  v[6],  a2); a3 = fma2(Pc0[7],  v[7],  a3);        \
        a0 = fma2(Pc0[8],  v[8],  a0); a1 = fma2(Pc0[9],  v[9],  a1);        \
        a2 = fma2(Pc0[10], v[10], a2); a3 = fma2(Pc0[11], v[11], a3);        \
        a0 = fma2(Pc0[12], v[12], a0);                                       \
        u64 q0 = mul2(Qc0[0], v[1]);  u64 q1 = mul2(Qc0[1], v[2]);           \
        u64 q2 = mul2(Qc0[2], v[3]);  u64 q3 = mul2(Qc0[3], v[4]);           \
        q0 = fma2(Qc0[4],  v[5],  q0); q1 = fma2(Qc0[5],  v[6],  q1);        \
        q2 = fma2(Qc0[6],  v[7],  q2); q3 = fma2(Qc0[7],  v[8],  q3);        \
        q0 = fma2(Qc0[8],  v[9],  q0); q1 = fma2(Qc0[9],  v[10], q1);        \
        q2 = fma2(Qc0[10], v[11], q2);                                       \
        u64 b0 = mul2(Pc1[0], v[1]);  u64 b1 = mul2(Pc1[1], v[2]);           \
        u64 b2 = mul2(Pc1[2], v[3]);  u64 b3 = mul2(Pc1[3], v[4]);           \
        b0 = fma2(Pc1[4],  v[5],  b0); b1 = fma2(Pc1[5],  v[6],  b1);        \
        b2 = fma2(Pc1[6],  v[7],  b2); b3 = fma2(Pc1[7],  v[8],  b3);        \
        b0 = fma2(Pc1[8],  v[9],  b0); b1 = fma2(Pc1[9],  v[10], b1);        \
        b2 = fma2(Pc1[10], v[11], b2); b3 = fma2(Pc1[11], v[12], b3);        \
        b0 = fma2(Pc1[12], v[13], b0);                                       \
        u64 r0 = mul2(Qc1[0], v[2]);  u64 r1 = mul2(Qc1[1], v[3]);           \
        u64 r2 = mul2(Qc1[2], v[4]);  u64 r3 = mul2(Qc1[3], v[5]);           \
        r0 = fma2(Qc1[4],  v[6],  r0); r1 = fma2(Qc1[5],  v[7],  r1);        \
        r2 = fma2(Qc1[6],  v[8],  r2); r3 = fma2(Qc1[7],  v[9],  r3);        \
        r0 = fma2(Qc1[8],  v[10], r0); r1 = fma2(Qc1[9],  v[11], r1);        \
        r2 = fma2(Qc1[10], v[12], r2);                                       \
        u64 uP0 = add2(add2(a0, a1), add2(a2, a3));                          \
        u64 uQ0 = add2(add2(q0, q1), add2(q2, q3));                          \
        u64 uP1 = add2(add2(b0, b1), add2(b2, b3));                          \
        u64 uQ1 = add2(add2(r0, r1), add2(r2, r3));                          \
        F2U U0, V0, U1, V1; U0.u = uP0; V0.u = uQ0; U1.u = uP1; V1.u = uQ1;  \
        y0p = pk2(U0.f.x - V0.f.y, U0.f.y + V0.f.x);                         \
        y1p = pk2(U1.f.x - V1.f.y, U1.f.y + V1.f.x);                         \
        float4 sv; sv.x = lo2(y0p); sv.y = hi2(y0p);                         \
        sv.z = lo2(y1p); sv.w = hi2(y1p);                                    \
        *(WDST) = sv;                                                        \
        __syncthreads();                                                     \
    }

    const int nitv = n_save - 1;
    for (int itv = 0; itv < nitv; ++itv) {
        #pragma unroll 1
        for (int s2 = 0; s2 < N_INNER / 2; ++s2) {
            STEP(RA, WB)          // A -> B
            STEP(RB, WA)          // B -> A
        }
        if (p0 < NPTS) {
            int row = (itv + 1) * NPTS + p0;
            out[row]            = lo2(y0p);  out[row + 1]        = lo2(y1p);
            out[half + row]     = hi2(y0p);  out[half + row + 1] = hi2(y1p);
        }
    }
#undef STEP
}

extern "C" void kernel_launch(void* const* d_in, const int* in_sizes, int n_in,
                              void* d_out, int out_size)
{
    int p_idx = 1, t_idx = 0;
    if (n_in >= 2 && in_sizes[0] == 2 && in_sizes[1] != 2) { p_idx = 0; t_idx = 1; }
    const float* params = (const float*)d_in[p_idx];
    const int n_save = in_sizes[t_idx];
    pe_kernel<<<1, NTH>>>(params, (float*)d_out, n_save);
}

// round 10
// speedup vs baseline: 2.8886x; 1.2419x over previous
#include <cuda_runtime.h>
#include <math.h>

// NarrowParabolicEq — SQUARED banded Dopri5 step operator S^2, 2 points/thread.
// S = P + iQ, P,Q real polynomials in the same tridiagonal Z (so they commute):
// S^2 = (P^2 - Q^2) + i*(2PQ), real band radius 12 / 11. Each thread builds its
// two S^2 band rows in registers (12-deep recurrence, literal indices only).
// Main loop: one 25-pt banded apply + ONE __syncthreads per TWO RK steps
// (1000 barriers total, was 2000). 256 threads, scalar FFMA dot products,
// aligned LDS.128/STS.128. Planar complex output.

#define NPTS 500
#define NTH  256
#define YSLOTS 540        // u64 slots; point q -> slot q+12 (12 pad each side)
#define N_INNER 10

typedef unsigned long long u64;

__device__ __forceinline__ void coeffs_at(int q, double K0d, double refc, double refd,
                                          float* hcli, float* hch2)
{
    if (q >= 1 && q <= NPTS - 2) {
        double dx = 2000.0 / 499.0;
        double cli = (1.0 / (dx * dx)) / (2.0 * K0d);
        double z  = 2000.0 * (double)q / 499.0;
        double zz = 2.0 * (z - refd) / refd;
        double c  = refc * (1.0 + 0.00737 * (zz - 1.0 + exp(-zz)));
        double het = (1500.0 / c) * (1500.0 / c) - 1.0;
        double ch = K0d * het;
        *hcli = (float)(0.1 * cli);
        *hch2 = (float)(0.1 * (ch - 2.0 * cli));
    } else {
        *hcli = 0.0f; *hch2 = 0.0f;
    }
}

// Band rows of S^2: P2 = P^2-Q^2 (offsets -12..+12) and Q2 = 2PQ (-11..+11),
// built by the 12-deep register recurrence around point q. Literal indices only.
__device__ __forceinline__ void build_row2(int q, double K0d, double refc, double refd,
                                           float P2r[25], float Q2r[23])
{
    float cliA[25], ch2A[25];
    #pragma unroll
    for (int j = 0; j < 25; j++)
        coeffs_at(q - 12 + j, K0d, refc, refd, &cliA[j], &ch2A[j]);

    float w[25], Qt[25];
    #pragma unroll
    for (int j = 0; j < 25; j++) { w[j] = 0.f; P2r[j] = 0.f; Qt[j] = 0.f; }
    w[12] = 1.f; P2r[12] = 1.f;

    #pragma unroll
    for (int k = 1; k <= 12; k++) {
        float nw[25];
        #pragma unroll
        for (int o = 0; o < 25; o++) {
            float acc = w[o] * ch2A[o];
            if (o > 0)  acc += w[o - 1] * cliA[o - 1];
            if (o < 24) acc += w[o + 1] * cliA[o + 1];
            nw[o] = acc;
        }
        #pragma unroll
        for (int o = 0; o < 25; o++) {
            w[o] = nw[o];
            // literal coefficients of P^2-Q^2 (even k) and 2PQ (odd k)
            if (k == 1)  Qt[o]  += 2.0f * nw[o];
            if (k == 2)  P2r[o] += -2.0f * nw[o];
            if (k == 3)  Qt[o]  += (float)(-4.0/3.0) * nw[o];
            if (k == 4)  P2r[o] += (float)(2.0/3.0) * nw[o];
            if (k == 5)  Qt[o]  += (float)(4.0/15.0) * nw[o];
            if (k == 6)  P2r[o] += (float)(-161.0/1800.0) * nw[o];
            if (k == 7)  Qt[o]  += (float)(-23.0/900.0) * nw[o];
            if (k == 8)  P2r[o] += (float)(89.0/14400.0) * nw[o];
            if (k == 9)  Qt[o]  += (float)(1.0/800.0) * nw[o];
            if (k == 10) P2r[o] += (float)(-1.0/4800.0) * nw[o];
            if (k == 11) Qt[o]  += (float)(-1.0/36000.0) * nw[o];
            if (k == 12) P2r[o] += (float)(1.0/360000.0) * nw[o];
        }
    }
    #pragma unroll
    for (int j = 0; j < 23; j++) Q2r[j] = Qt[j + 1];   // offsets -11..+11
}

__global__ __launch_bounds__(NTH, 1)
void pe_kernel(const float* __restrict__ params, float* __restrict__ out, int n_save)
{
    __shared__ __align__(16) u64 YA[YSLOTS];
    __shared__ __align__(16) u64 YB[YSLOTS];

    const int t  = threadIdx.x;
    const int p0 = 2 * t;
    const int half = n_save * NPTS;

    const double PI  = 3.14159265358979323846;
    const double K0d = 2.0 * PI * 50.0 / 1500.0;
    const double refc = (double)params[0];
    const double refd = (double)params[1];

    // ---- initial field ----
    float y0r = 0.f, y0i = 0.f, y1r = 0.f, y1i = 0.f;
    if (p0 < NPTS) {
        double ww  = sqrt(2.0 * log(2.0)) / (K0d * sin(PI / 180.0 * 1.5));
        double amp = 1.0 / (sqrt(PI) * ww);
        double z = 2000.0 * (double)p0 / 499.0;
        double a = (z - 100.0) / ww;
        y0r = (float)(amp * exp(-a * a));
        z = 2000.0 * (double)(p0 + 1) / 499.0;
        a = (z - 100.0) / ww;
        y1r = (float)(amp * exp(-a * a));
        out[p0] = y0r;  out[p0 + 1] = y1r;
        out[half + p0] = 0.f;  out[half + p0 + 1] = 0.f;
    }

    // ---- S^2 band rows for both owned points ----
    float P2a[25], Q2a[23], P2b[25], Q2b[23];
    build_row2(p0,     K0d, refc, refd, P2a, Q2a);
    build_row2(p0 + 1, K0d, refc, refd, P2b, Q2b);

    // ---- buffers ----
    for (int j = t; j < YSLOTS; j += NTH) { YA[j] = 0ull; YB[j] = 0ull; }
    __syncthreads();
    {
        union { float2 f; u64 u; } c0, c1;
        c0.f = make_float2(y0r, y0i); c1.f = make_float2(y1r, y1i);
        YA[p0 + 12] = c0.u;
        YA[p0 + 13] = c1.u;
    }
    __syncthreads();

    const float4* RA = ((const float4*)YA) + t;   // u64 slots 2t .. 2t+25
    const float4* RB = ((const float4*)YB) + t;
    float4* WA = ((float4*)YA) + (t + 6);         // u64 slots 2t+12, 2t+13
    float4* WB = ((float4*)YB) + (t + 6);

    // One S^2 application (2 RK steps): halo = points p0-12..p0+13 (26 u64).
    // Taps: pt a: P2 -> v[0..24], Q2 -> v[1..23]; pt b: +1 shifted.
#define STEP2(RSRC, WDST)                                                    \
    {                                                                        \
        float vr[26], vi[26];                                                \
        _Pragma("unroll")                                                    \
        for (int j = 0; j < 13; j++) {                                       \
            float4 f = (RSRC)[j];                                            \
            vr[2*j] = f.x; vi[2*j] = f.y;                                    \
            vr[2*j+1] = f.z; vi[2*j+1] = f.w;                                \
        }                                                                    \
        float pr0 = 0.f, pi0 = 0.f, qr0 = 0.f, qi0 = 0.f;                    \
        float pr1 = 0.f, pi1 = 0.f, qr1 = 0.f, qi1 = 0.f;                    \
        _Pragma("unroll")                                                    \
        for (int j = 0; j < 25; j++) {                                       \
            pr0 += P2a[j] * vr[j];      pi0 += P2a[j] * vi[j];               \
            pr1 += P2b[j] * vr[j + 1];  pi1 += P2b[j] * vi[j + 1];           \
        }                                                                    \
        _Pragma("unroll")                                                    \
        for (int j = 0; j < 23; j++) {                                       \
            qr0 += Q2a[j] * vr[j + 1];  qi0 += Q2a[j] * vi[j + 1];           \
            qr1 += Q2b[j] * vr[j + 2];  qi1 += Q2b[j] * vi[j + 2];           \
        }                                                                    \
        y0r = pr0 - qi0;  y0i = pi0 + qr0;                                   \
        y1r = pr1 - qi1;  y1i = pi1 + qr1;                                   \
        float4 sv; sv.x = y0r; sv.y = y0i; sv.z = y1r; sv.w = y1i;           \
        *(WDST) = sv;                                                        \
        __syncthreads();                                                     \
    }

#define SAVE(ROWI)                                                           \
    if (p0 < NPTS) {                                                         \
        int row = (ROWI) * NPTS + p0;                                        \
        out[row]            = y0r;  out[row + 1]        = y1r;               \
        out[half + row]     = y0i;  out[half + row + 1] = y1i;               \
    }

    const int nitv = n_save - 1;
    const int pairs = nitv / 2;
    for (int it2 = 0; it2 < pairs; ++it2) {
        // interval 1: 5 x S^2 starting from A, ends in B
        STEP2(RA, WB) STEP2(RB, WA) STEP2(RA, WB) STEP2(RB, WA) STEP2(RA, WB)
        SAVE(2 * it2 + 1)
        // interval 2: 5 x S^2 starting from B, ends in A
        STEP2(RB, WA) STEP2(RA, WB) STEP2(RB, WA) STEP2(RA, WB) STEP2(RB, WA)
        SAVE(2 * it2 + 2)
    }
    if (nitv & 1) {   // odd tail (not hit for n_save=201; kept for generality)
        STEP2(RA, WB) STEP2(RB, WA) STEP2(RA, WB) STEP2(RB, WA) STEP2(RA, WB)
        SAVE(nitv)
    }
#undef STEP2
#undef SAVE
}

extern "C" void kernel_launch(void* const* d_in, const int* in_sizes, int n_in,
                              void* d_out, int out_size)
{
    int p_idx = 1, t_idx = 0;
    if (n_in >= 2 && in_sizes[0] == 2 && in_sizes[1] != 2) { p_idx = 0; t_idx = 1; }
    const float* params = (const float*)d_in[p_idx];
    const int n_save = in_sizes[t_idx];
    pe_kernel<<<1, NTH>>>(params, (float*)d_out, n_save);
}

// round 11
// speedup vs baseline: 5.3337x; 1.8465x over previous
#include <cuda_runtime.h>
#include <math.h>

// NarrowParabolicEq — S^2 banded operator TRUNCATED to radius 4, packed f32x2.
// S = P + iQ (polynomials in tridiagonal Z, commute): S^2 = (P^2-Q^2) + i(2PQ).
// Z off-diag = 0.0149, so band entries decay as 0.0149^|o|: offset>=5 entries
// are < 2e-10 (sub-fp32-epsilon) -> truncated exactly. Rows built EXACTLY
// (25-wide, 12-deep register recurrence), only the application is truncated.
// 9 taps per point for both parts, packed (re,im) f32x2 arithmetic:
// 36 fma2/thread per application, one barrier per TWO RK steps (1000 total).
// 256 threads, 2 points/thread, 5 aligned LDS.128 halo + 1 STS.128.

#define NPTS 500
#define NTH  256
#define YSLOTS 520        // u64 slots; point q -> slot q+4 (4 pad each side)
#define N_INNER 10

typedef unsigned long long u64;
union F2U { float2 f; u64 u; };

__device__ __forceinline__ u64 pk2(float lo, float hi) { F2U x; x.f.x = lo; x.f.y = hi; return x.u; }
__device__ __forceinline__ float lo2(u64 v) { F2U a; a.u = v; return a.f.x; }
__device__ __forceinline__ float hi2(u64 v) { F2U a; a.u = v; return a.f.y; }

__device__ __forceinline__ u64 fma2(u64 a, u64 b, u64 c)
{ u64 d; asm("fma.rn.f32x2 %0,%1,%2,%3;" : "=l"(d) : "l"(a), "l"(b), "l"(c)); return d; }
__device__ __forceinline__ u64 add2(u64 a, u64 b)
{ u64 d; asm("add.rn.f32x2 %0,%1,%2;" : "=l"(d) : "l"(a), "l"(b)); return d; }
__device__ __forceinline__ u64 mul2(u64 a, u64 b)
{ u64 d; asm("mul.rn.f32x2 %0,%1,%2;" : "=l"(d) : "l"(a), "l"(b)); return d; }

__device__ __forceinline__ void coeffs_at(int q, double K0d, double refc, double refd,
                                          float* hcli, float* hch2)
{
    if (q >= 1 && q <= NPTS - 2) {
        double dx = 2000.0 / 499.0;
        double cli = (1.0 / (dx * dx)) / (2.0 * K0d);
        double z  = 2000.0 * (double)q / 499.0;
        double zz = 2.0 * (z - refd) / refd;
        double c  = refc * (1.0 + 0.00737 * (zz - 1.0 + exp(-zz)));
        double het = (1500.0 / c) * (1500.0 / c) - 1.0;
        double ch = K0d * het;
        *hcli = (float)(0.1 * cli);
        *hch2 = (float)(0.1 * (ch - 2.0 * cli));
    } else {
        *hcli = 0.0f; *hch2 = 0.0f;
    }
}

// Exact S^2 band rows (P2 = P^2-Q^2, Q2 = 2PQ) around point q, offset-indexed
// o = offset+12 in [0,25). Identical algebra to the passing full-band kernel.
__device__ __forceinline__ void build_row2(int q, double K0d, double refc, double refd,
                                           float P2r[25], float Q2r[25])
{
    float cliA[25], ch2A[25];
    #pragma unroll
    for (int j = 0; j < 25; j++)
        coeffs_at(q - 12 + j, K0d, refc, refd, &cliA[j], &ch2A[j]);

    float w[25];
    #pragma unroll
    for (int j = 0; j < 25; j++) { w[j] = 0.f; P2r[j] = 0.f; Q2r[j] = 0.f; }
    w[12] = 1.f; P2r[12] = 1.f;

    #pragma unroll
    for (int k = 1; k <= 12; k++) {
        float nw[25];
        #pragma unroll
        for (int o = 0; o < 25; o++) {
            float acc = w[o] * ch2A[o];
            if (o > 0)  acc += w[o - 1] * cliA[o - 1];
            if (o < 24) acc += w[o + 1] * cliA[o + 1];
            nw[o] = acc;
        }
        #pragma unroll
        for (int o = 0; o < 25; o++) {
            w[o] = nw[o];
            if (k == 1)  Q2r[o] += 2.0f * nw[o];
            if (k == 2)  P2r[o] += -2.0f * nw[o];
            if (k == 3)  Q2r[o] += (float)(-4.0/3.0) * nw[o];
            if (k == 4)  P2r[o] += (float)(2.0/3.0) * nw[o];
            if (k == 5)  Q2r[o] += (float)(4.0/15.0) * nw[o];
            if (k == 6)  P2r[o] += (float)(-161.0/1800.0) * nw[o];
            if (k == 7)  Q2r[o] += (float)(-23.0/900.0) * nw[o];
            if (k == 8)  P2r[o] += (float)(89.0/14400.0) * nw[o];
            if (k == 9)  Q2r[o] += (float)(1.0/800.0) * nw[o];
            if (k == 10) P2r[o] += (float)(-1.0/4800.0) * nw[o];
            if (k == 11) Q2r[o] += (float)(-1.0/36000.0) * nw[o];
            if (k == 12) P2r[o] += (float)(1.0/360000.0) * nw[o];
        }
    }
}

__global__ __launch_bounds__(NTH, 1)
void pe_kernel(const float* __restrict__ params, float* __restrict__ out, int n_save)
{
    __shared__ __align__(16) u64 YA[YSLOTS];
    __shared__ __align__(16) u64 YB[YSLOTS];

    const int t  = threadIdx.x;
    const int p0 = 2 * t;
    const int half = n_save * NPTS;

    const double PI  = 3.14159265358979323846;
    const double K0d = 2.0 * PI * 50.0 / 1500.0;
    const double refc = (double)params[0];
    const double refd = (double)params[1];

    // ---- initial field ----
    float y0r = 0.f, y1r = 0.f;
    if (p0 < NPTS) {
        double ww  = sqrt(2.0 * log(2.0)) / (K0d * sin(PI / 180.0 * 1.5));
        double amp = 1.0 / (sqrt(PI) * ww);
        double z = 2000.0 * (double)p0 / 499.0;
        double a = (z - 100.0) / ww;
        y0r = (float)(amp * exp(-a * a));
        z = 2000.0 * (double)(p0 + 1) / 499.0;
        a = (z - 100.0) / ww;
        y1r = (float)(amp * exp(-a * a));
        out[p0] = y0r;  out[p0 + 1] = y1r;
        out[half + p0] = 0.f;  out[half + p0 + 1] = 0.f;
    }

    // ---- exact rows, truncate to offsets -4..+4, pack ----
    u64 Pa[9], Qa[9], Pb[9], Qb[9];
    {
        float P2[25], Q2[25];
        build_row2(p0, K0d, refc, refd, P2, Q2);
        #pragma unroll
        for (int j = 0; j < 9; j++) { Pa[j] = pk2(P2[8 + j], P2[8 + j]); Qa[j] = pk2(Q2[8 + j], Q2[8 + j]); }
        build_row2(p0 + 1, K0d, refc, refd, P2, Q2);
        #pragma unroll
        for (int j = 0; j < 9; j++) { Pb[j] = pk2(P2[8 + j], P2[8 + j]); Qb[j] = pk2(Q2[8 + j], Q2[8 + j]); }
    }

    // ---- buffers ----
    for (int j = t; j < YSLOTS; j += NTH) { YA[j] = 0ull; YB[j] = 0ull; }
    __syncthreads();
    YA[p0 + 4] = pk2(y0r, 0.f);
    YA[p0 + 5] = pk2(y1r, 0.f);
    __syncthreads();

    const float4* RA = ((const float4*)YA) + t;   // u64 slots 2t .. 2t+9
    const float4* RB = ((const float4*)YB) + t;
    float4* WA = ((float4*)YA) + (t + 2);         // u64 slots 2t+4, 2t+5
    float4* WB = ((float4*)YB) + (t + 2);

    u64 y0p = pk2(y0r, 0.f), y1p = pk2(y1r, 0.f);

    // One S^2 application (2 RK steps). Halo = points p0-4..p0+5 = v[0..9].
    // Pt a taps v[0..8]; pt b taps v[1..9].
#define STEP2(RSRC, WDST)                                                    \
    {                                                                        \
        u64 v[10];                                                           \
        _Pragma("unroll")                                                    \
        for (int j = 0; j < 5; j++) {                                        \
            float4 f = (RSRC)[j];                                            \
            v[2*j] = pk2(f.x, f.y); v[2*j + 1] = pk2(f.z, f.w);              \
        }                                                                    \
        u64 pa0 = mul2(Pa[0], v[0]);   u64 pa1 = mul2(Pa[1], v[1]);          \
        pa0 = fma2(Pa[2], v[2], pa0);  pa1 = fma2(Pa[3], v[3], pa1);         \
        pa0 = fma2(Pa[4], v[4], pa0);  pa1 = fma2(Pa[5], v[5], pa1);         \
        pa0 = fma2(Pa[6], v[6], pa0);  pa1 = fma2(Pa[7], v[7], pa1);         \
        pa0 = fma2(Pa[8], v[8], pa0);                                        \
        u64 qa0 = mul2(Qa[0], v[0]);   u64 qa1 = mul2(Qa[1], v[1]);          \
        qa0 = fma2(Qa[2], v[2], qa0);  qa1 = fma2(Qa[3], v[3], qa1);         \
        qa0 = fma2(Qa[4], v[4], qa0);  qa1 = fma2(Qa[5], v[5], qa1);         \
        qa0 = fma2(Qa[6], v[6], qa0);  qa1 = fma2(Qa[7], v[7], qa1);         \
        qa0 = fma2(Qa[8], v[8], qa0);                                        \
        u64 pb0 = mul2(Pb[0], v[1]);   u64 pb1 = mul2(Pb[1], v[2]);          \
        pb0 = fma2(Pb[2], v[3], pb0);  pb1 = fma2(Pb[3], v[4], pb1);         \
        pb0 = fma2(Pb[4], v[5], pb0);  pb1 = fma2(Pb[5], v[6], pb1);         \
        pb0 = fma2(Pb[6], v[7], pb0);  pb1 = fma2(Pb[7], v[8], pb1);         \
        pb0 = fma2(Pb[8], v[9], pb0);                                        \
        u64 qb0 = mul2(Qb[0], v[1]);   u64 qb1 = mul2(Qb[1], v[2]);          \
        qb0 = fma2(Qb[2], v[3], qb0);  qb1 = fma2(Qb[3], v[4], qb1);         \
        qb0 = fma2(Qb[4], v[5], qb0);  qb1 = fma2(Qb[5], v[6], qb1);         \
        qb0 = fma2(Qb[6], v[7], qb0);  qb1 = fma2(Qb[7], v[8], qb1);         \
        qb0 = fma2(Qb[8], v[9], qb0);                                        \
        u64 uP0 = add2(pa0, pa1);  u64 uQ0 = add2(qa0, qa1);                 \
        u64 uP1 = add2(pb0, pb1);  u64 uQ1 = add2(qb0, qb1);                 \
        F2U U0, V0, U1, V1; U0.u = uP0; V0.u = uQ0; U1.u = uP1; V1.u = uQ1;  \
        y0p = pk2(U0.f.x - V0.f.y, U0.f.y + V0.f.x);                         \
        y1p = pk2(U1.f.x - V1.f.y, U1.f.y + V1.f.x);                         \
        float4 sv; sv.x = lo2(y0p); sv.y = hi2(y0p);                         \
        sv.z = lo2(y1p); sv.w = hi2(y1p);                                    \
        *(WDST) = sv;                                                        \
        __syncthreads();                                                     \
    }

#define SAVE(ROWI)                                                           \
    if (p0 < NPTS) {                                                         \
        int row = (ROWI) * NPTS + p0;                                        \
        out[row]            = lo2(y0p);  out[row + 1]        = lo2(y1p);     \
        out[half + row]     = hi2(y0p);  out[half + row + 1] = hi2(y1p);     \
    }

    const int nitv = n_save - 1;
    const int pairs = nitv / 2;
    for (int it2 = 0; it2 < pairs; ++it2) {
        STEP2(RA, WB) STEP2(RB, WA) STEP2(RA, WB) STEP2(RB, WA) STEP2(RA, WB)
        SAVE(2 * it2 + 1)
        STEP2(RB, WA) STEP2(RA, WB) STEP2(RB, WA) STEP2(RA, WB) STEP2(RB, WA)
        SAVE(2 * it2 + 2)
    }
    if (nitv & 1) {
        STEP2(RA, WB) STEP2(RB, WA) STEP2(RA, WB) STEP2(RB, WA) STEP2(RA, WB)
        SAVE(nitv)
    }
#undef STEP2
#undef SAVE
}

extern "C" void kernel_launch(void* const* d_in, const int* in_sizes, int n_in,
                              void* d_out, int out_size)
{
    int p_idx = 1, t_idx = 0;
    if (n_in >= 2 && in_sizes[0] == 2 && in_sizes[1] != 2) { p_idx = 0; t_idx = 1; }
    const float* params = (const float*)d_in[p_idx];
    const int n_save = in_sizes[t_idx];
    pe_kernel<<<1, NTH>>>(params, (float*)d_out, n_save);
}

// round 12
// speedup vs baseline: 12.6228x; 2.3666x over previous
#include <cuda_runtime.h>
#include <math.h>

// NarrowParabolicEq — ONE banded operator application per save interval.
// S = R(hM) is the Dopri5 step; a save interval is S^10 = R(z)^10, z = i*zeta.
// Band entries of S^10 decay as (10*h*cli)^o/o! -> offset>=7 entries < 2e-10:
// truncate to radius 6 (13 taps). Rows built per-thread: degree-14 coefficients
// of R^10 by double convolution, parity-split into real P (even i^m) and
// Q (odd i^m), then 19-wide x 14-deep zeta-power register recurrence.
// Main loop: 200 applications, ONE __syncthreads each (was 1000).
// 256 threads, 2 points/thread, packed f32x2, 7 aligned LDS.128 + 1 STS.128.

#define NPTS 500
#define NTH  256
#define YSLOTS 528        // u64 slots; point q -> slot q+6 (6 pad each side)

typedef unsigned long long u64;
union F2U { float2 f; u64 u; };

__device__ __forceinline__ u64 pk2(float lo, float hi) { F2U x; x.f.x = lo; x.f.y = hi; return x.u; }
__device__ __forceinline__ float lo2(u64 v) { F2U a; a.u = v; return a.f.x; }
__device__ __forceinline__ float hi2(u64 v) { F2U a; a.u = v; return a.f.y; }

__device__ __forceinline__ u64 fma2(u64 a, u64 b, u64 c)
{ u64 d; asm("fma.rn.f32x2 %0,%1,%2,%3;" : "=l"(d) : "l"(a), "l"(b), "l"(c)); return d; }
__device__ __forceinline__ u64 add2(u64 a, u64 b)
{ u64 d; asm("add.rn.f32x2 %0,%1,%2;" : "=l"(d) : "l"(a), "l"(b)); return d; }
__device__ __forceinline__ u64 mul2(u64 a, u64 b)
{ u64 d; asm("mul.rn.f32x2 %0,%1,%2;" : "=l"(d) : "l"(a), "l"(b)); return d; }

__device__ __forceinline__ void coeffs_at(int q, double K0d, double refc, double refd,
                                          float* hcli, float* hch2)
{
    if (q >= 1 && q <= NPTS - 2) {
        double dx = 2000.0 / 499.0;
        double cli = (1.0 / (dx * dx)) / (2.0 * K0d);
        double z  = 2000.0 * (double)q / 499.0;
        double zz = 2.0 * (z - refd) / refd;
        double c  = refc * (1.0 + 0.00737 * (zz - 1.0 + exp(-zz)));
        double het = (1500.0 / c) * (1500.0 / c) - 1.0;
        double ch = K0d * het;
        *hcli = (float)(0.1 * cli);
        *hch2 = (float)(0.1 * (ch - 2.0 * cli));
    } else {
        *hcli = 0.0f; *hch2 = 0.0f;
    }
}

// Band row (offsets -6..+6) of the S^10 operator around point q.
// pc[m]/qc[m]: parity-folded real coefficients of R^10 (pc even m, qc odd m).
__device__ __forceinline__ void build_taps(int q, double K0d, double refc, double refd,
                                           const float* pc, const float* qc,
                                           float Pt[13], float Qt[13])
{
    float cliA[19], ch2A[19];
    #pragma unroll
    for (int j = 0; j < 19; j++)
        coeffs_at(q - 9 + j, K0d, refc, refd, &cliA[j], &ch2A[j]);

    float w[19];
    #pragma unroll
    for (int j = 0; j < 19; j++) w[j] = 0.f;
    w[9] = 1.f;
    #pragma unroll
    for (int j = 0; j < 13; j++) { Pt[j] = 0.f; Qt[j] = 0.f; }
    Pt[6] = pc[0];   // m = 0 term (identity), pc[0] = 1

    #pragma unroll
    for (int k = 1; k <= 14; k++) {
        float nw[19];
        #pragma unroll
        for (int o = 0; o < 19; o++) {
            float acc = w[o] * ch2A[o];
            if (o > 0)  acc += w[o - 1] * cliA[o - 1];
            if (o < 18) acc += w[o + 1] * cliA[o + 1];
            nw[o] = acc;
        }
        #pragma unroll
        for (int o = 0; o < 19; o++) w[o] = nw[o];
        // accumulate only the 13 center taps (window idx o2+3 = offset o2-6)
        #pragma unroll
        for (int o2 = 0; o2 < 13; o2++) {
            Pt[o2] += pc[k] * w[o2 + 3];   // pc[k]=0 for odd k
            Qt[o2] += qc[k] * w[o2 + 3];   // qc[k]=0 for even k
        }
    }
}

__global__ __launch_bounds__(NTH, 1)
void pe_kernel(const float* __restrict__ params, float* __restrict__ out, int n_save)
{
    __shared__ __align__(16) u64 YA[YSLOTS];
    __shared__ __align__(16) u64 YB[YSLOTS];

    const int t  = threadIdx.x;
    const int p0 = 2 * t;
    const int half = n_save * NPTS;

    const double PI  = 3.14159265358979323846;
    const double K0d = 2.0 * PI * 50.0 / 1500.0;
    const double refc = (double)params[0];
    const double refd = (double)params[1];

    // ---- initial field ----
    float y0r = 0.f, y1r = 0.f;
    if (p0 < NPTS) {
        double ww  = sqrt(2.0 * log(2.0)) / (K0d * sin(PI / 180.0 * 1.5));
        double amp = 1.0 / (sqrt(PI) * ww);
        double z = 2000.0 * (double)p0 / 499.0;
        double a = (z - 100.0) / ww;
        y0r = (float)(amp * exp(-a * a));
        z = 2000.0 * (double)(p0 + 1) / 499.0;
        a = (z - 100.0) / ww;
        y1r = (float)(amp * exp(-a * a));
        out[p0] = y0r;  out[p0 + 1] = y1r;
        out[half + p0] = 0.f;  out[half + p0 + 1] = 0.f;
    }

    // ---- degree-14 coefficients of R^10 by double convolution ----
    float pcF[15], qcF[15];
    {
        double cD[7] = {1.0, 1.0, 0.5, 1.0/6.0, 1.0/24.0, 1.0/120.0, 1.0/600.0};
        double R2[15], R4[15], R8[15], R10[15];
        for (int m = 0; m < 15; m++) {
            double s = 0.0;
            for (int j = 0; j <= 6; j++)
                if (m - j >= 0 && m - j <= 6) s += cD[j] * cD[m - j];
            R2[m] = s;
        }
        for (int m = 0; m < 15; m++) {
            double s = 0.0;
            for (int j = 0; j <= m; j++) s += R2[j] * R2[m - j];
            R4[m] = s;
        }
        for (int m = 0; m < 15; m++) {
            double s = 0.0;
            for (int j = 0; j <= m; j++) s += R4[j] * R4[m - j];
            R8[m] = s;
        }
        for (int m = 0; m < 15; m++) {
            double s = 0.0;
            for (int j = 0; j <= m; j++) s += R8[j] * R2[m - j];
            R10[m] = s;
        }
        // fold i^m: P gets even m with sign (-1)^{m/2}; Q gets odd m with (-1)^{(m-1)/2}
        for (int m = 0; m < 15; m++) {
            if ((m & 1) == 0) {
                pcF[m] = (float)(((m & 3) == 0) ? R10[m] : -R10[m]);
                qcF[m] = 0.f;
            } else {
                qcF[m] = (float)(((m & 3) == 1) ? R10[m] : -R10[m]);
                pcF[m] = 0.f;
            }
        }
    }

    // ---- band taps for both owned points, packed ----
    u64 Pa[13], Qa[13], Pb[13], Qb[13];
    {
        float Pt[13], Qt[13];
        build_taps(p0, K0d, refc, refd, pcF, qcF, Pt, Qt);
        #pragma unroll
        for (int j = 0; j < 13; j++) { Pa[j] = pk2(Pt[j], Pt[j]); Qa[j] = pk2(Qt[j], Qt[j]); }
        build_taps(p0 + 1, K0d, refc, refd, pcF, qcF, Pt, Qt);
        #pragma unroll
        for (int j = 0; j < 13; j++) { Pb[j] = pk2(Pt[j], Pt[j]); Qb[j] = pk2(Qt[j], Qt[j]); }
    }

    // ---- buffers ----
    for (int j = t; j < YSLOTS; j += NTH) { YA[j] = 0ull; YB[j] = 0ull; }
    __syncthreads();
    YA[p0 + 6] = pk2(y0r, 0.f);
    YA[p0 + 7] = pk2(y1r, 0.f);
    __syncthreads();

    const float4* RA = ((const float4*)YA) + t;   // u64 slots 2t .. 2t+13
    const float4* RB = ((const float4*)YB) + t;
    float4* WA = ((float4*)YA) + (t + 3);         // u64 slots 2t+6, 2t+7
    float4* WB = ((float4*)YB) + (t + 3);

    u64 y0p = pk2(y0r, 0.f), y1p = pk2(y1r, 0.f);

    // One S^10 application = one full save interval. Halo v[0..13] = points
    // p0-6..p0+7. Pt a taps v[0..12]; pt b taps v[1..13].
#define STEP(RSRC, WDST)                                                     \
    {                                                                        \
        u64 v[14];                                                           \
        _Pragma("unroll")                                                    \
        for (int j = 0; j < 7; j++) {                                        \
            float4 f = (RSRC)[j];                                            \
            v[2*j] = pk2(f.x, f.y); v[2*j + 1] = pk2(f.z, f.w);              \
        }                                                                    \
        u64 pa0 = mul2(Pa[0], v[0]);   u64 pa1 = mul2(Pa[1], v[1]);          \
        pa0 = fma2(Pa[2],  v[2],  pa0); pa1 = fma2(Pa[3],  v[3],  pa1);      \
        pa0 = fma2(Pa[4],  v[4],  pa0); pa1 = fma2(Pa[5],  v[5],  pa1);      \
        pa0 = fma2(Pa[6],  v[6],  pa0); pa1 = fma2(Pa[7],  v[7],  pa1);      \
        pa0 = fma2(Pa[8],  v[8],  pa0); pa1 = fma2(Pa[9],  v[9],  pa1);      \
        pa0 = fma2(Pa[10], v[10], pa0); pa1 = fma2(Pa[11], v[11], pa1);      \
        pa0 = fma2(Pa[12], v[12], pa0);                                      \
        u64 qa0 = mul2(Qa[0], v[0]);   u64 qa1 = mul2(Qa[1], v[1]);          \
        qa0 = fma2(Qa[2],  v[2],  qa0); qa1 = fma2(Qa[3],  v[3],  qa1);      \
        qa0 = fma2(Qa[4],  v[4],  qa0); qa1 = fma2(Qa[5],  v[5],  qa1);      \
        qa0 = fma2(Qa[6],  v[6],  qa0); qa1 = fma2(Qa[7],  v[7],  qa1);      \
        qa0 = fma2(Qa[8],  v[8],  qa0); qa1 = fma2(Qa[9],  v[9],  qa1);      \
        qa0 = fma2(Qa[10], v[10], qa0); qa1 = fma2(Qa[11], v[11], qa1);      \
        qa0 = fma2(Qa[12], v[12], qa0);                                      \
        u64 pb0 = mul2(Pb[0], v[1]);   u64 pb1 = mul2(Pb[1], v[2]);          \
        pb0 = fma2(Pb[2],  v[3],  pb0); pb1 = fma2(Pb[3],  v[4],  pb1);      \
        pb0 = fma2(Pb[4],  v[5],  pb0); pb1 = fma2(Pb[5],  v[6],  pb1);      \
        pb0 = fma2(Pb[6],  v[7],  pb0); pb1 = fma2(Pb[7],  v[8],  pb1);      \
        pb0 = fma2(Pb[8],  v[9],  pb0); pb1 = fma2(Pb[9],  v[10], pb1);      \
        pb0 = fma2(Pb[10], v[11], pb0); pb1 = fma2(Pb[11], v[12], pb1);      \
        pb0 = fma2(Pb[12], v[13], pb0);                                      \
        u64 qb0 = mul2(Qb[0], v[1]);   u64 qb1 = mul2(Qb[1], v[2]);          \
        qb0 = fma2(Qb[2],  v[3],  qb0); qb1 = fma2(Qb[3],  v[4],  qb1);      \
        qb0 = fma2(Qb[4],  v[5],  qb0); qb1 = fma2(Qb[5],  v[6],  qb1);      \
        qb0 = fma2(Qb[6],  v[7],  qb0); qb1 = fma2(Qb[7],  v[8],  qb1);      \
        qb0 = fma2(Qb[8],  v[9],  qb0); qb1 = fma2(Qb[9],  v[10], qb1);      \
        qb0 = fma2(Qb[10], v[11], qb0); qb1 = fma2(Qb[11], v[12], qb1);      \
        qb0 = fma2(Qb[12], v[13], qb0);                                      \
        u64 uP0 = add2(pa0, pa1);  u64 uQ0 = add2(qa0, qa1);                 \
        u64 uP1 = add2(pb0, pb1);  u64 uQ1 = add2(qb0, qb1);                 \
        F2U U0, V0, U1, V1; U0.u = uP0; V0.u = uQ0; U1.u = uP1; V1.u = uQ1;  \
        y0p = pk2(U0.f.x - V0.f.y, U0.f.y + V0.f.x);                         \
        y1p = pk2(U1.f.x - V1.f.y, U1.f.y + V1.f.x);                         \
        float4 sv; sv.x = lo2(y0p); sv.y = hi2(y0p);                         \
        sv.z = lo2(y1p); sv.w = hi2(y1p);                                    \
        *(WDST) = sv;                                                        \
        __syncthreads();                                                     \
    }

#define SAVE(ROWI)                                                           \
    if (p0 < NPTS) {                                                         \
        int row = (ROWI) * NPTS + p0;                                        \
        out[row]            = lo2(y0p);  out[row + 1]        = lo2(y1p);     \
        out[half + row]     = hi2(y0p);  out[half + row + 1] = hi2(y1p);     \
    }

    const int nitv = n_save - 1;
    const int pairs = nitv / 2;
    for (int it2 = 0; it2 < pairs; ++it2) {
        STEP(RA, WB)  SAVE(2 * it2 + 1)
        STEP(RB, WA)  SAVE(2 * it2 + 2)
    }
    if (nitv & 1) {
        STEP(RA, WB)  SAVE(nitv)
    }
#undef STEP
#undef SAVE
}

extern "C" void kernel_launch(void* const* d_in, const int* in_sizes, int n_in,
                              void* d_out, int out_size)
{
    int p_idx = 1, t_idx = 0;
    if (n_in >= 2 && in_sizes[0] == 2 && in_sizes[1] != 2) { p_idx = 0; t_idx = 1; }
    const float* params = (const float*)d_in[p_idx];
    const int n_save = in_sizes[t_idx];
    pe_kernel<<<1, NTH>>>(params, (float*)d_out, n_save);
}